// round 17
// baseline (speedup 1.0000x reference)
#include <cuda_runtime.h>
#include <cuda_fp16.h>
#include <cstdint>

// ============================================================================
// Router gate: x [32768, 2048] f32, w [64, 2048] f32.
// logits = x @ w^T ; probs = softmax ; top-8 vals + indices.
// Out: [probs N*64 | top_vals N*8 | indices(float) N*8]
//
// fp16 m16n8k16 MMA, 2-way split: x = xh+xm, w' = 256*w = wh+wm.
//   xh*wh -> chunk accumulator (k64), rebased into master via RN FADD
//   xh*wm + xm*wh -> separate small-magnitude accumulator
// R17: x PRE-SPLIT to packed fp16 (h,m) pairs at staging time (same smem
//      bytes as f32!) -> the 8 in-loop splitp chains vanish; A fragments
//      come from 4 direct LDS.64 per step. x double-buffered (STS by
//      staging threads post-barrier, LDG prefetched one chunk ahead).
//      B via 3-stage cp.async ring. TB=64, 256 threads, 2 CTAs/SM.
// ============================================================================

#define D 2048
#define TB 64             // tokens per CTA
#define NCH 32            // k64 chunks
#define BSTEP 4096        // B frag bytes per k16 step
#define BCHUNK 16384      // 4 steps = k64
#define XSTRIDE 272       // bytes per x row: 32 (h,m) uint2 pairs + 16 pad
#define XCH 17408         // 64 rows * 272
#define XBASE (3 * BCHUNK)            // 49152
#define SMEM_SZ (XBASE + 2 * XCH)     // 83968 -> 2 CTAs/SM
#define EPI_STRIDE 68
#define OSCALE 0.00390625f            // 2^-8, exact

// weights scaled x256, split into fp16 h/m, HMMA B-fragment order:
// [step(128)][tile(8)][lane(32)] x uint4(bh_klo, bh_khi, bm_klo, bm_khi)
__device__ __align__(16) unsigned char g_bfrag[128 * BSTEP];

static __device__ __forceinline__ uint32_t smem_u32(const void* p) {
    uint32_t a;
    asm("{ .reg .u64 t; cvta.to.shared.u64 t, %1; cvt.u32.u64 %0, t; }"
        : "=r"(a) : "l"(p));
    return a;
}
// split a float pair into fp16 hi + fp16 residual, packed f16x2
static __device__ __forceinline__ void splitp(float a, float b,
                                              uint32_t& h, uint32_t& m) {
    __half2 h2 = __floats2half2_rn(a, b);
    float2 hf = __half22float2(h2);
    __half2 m2 = __floats2half2_rn(a - hf.x, b - hf.y);
    h = *reinterpret_cast<uint32_t*>(&h2);
    m = *reinterpret_cast<uint32_t*>(&m2);
}

#define MMA(d, a, b0_, b1_) \
    asm volatile("mma.sync.aligned.m16n8k16.row.col.f32.f16.f16.f32 " \
        "{%0,%1,%2,%3}, {%4,%5,%6,%7}, {%8,%9}, {%0,%1,%2,%3};" \
        : "+f"((d)[0]), "+f"((d)[1]), "+f"((d)[2]), "+f"((d)[3]) \
        : "r"((a)[0]), "r"((a)[1]), "r"((a)[2]), "r"((a)[3]), "r"(b0_), "r"(b1_))
#define MMA_ZC(d, a, b0_, b1_) \
    asm volatile("mma.sync.aligned.m16n8k16.row.col.f32.f16.f16.f32 " \
        "{%0,%1,%2,%3}, {%4,%5,%6,%7}, {%8,%9}, {%10,%10,%10,%10};" \
        : "=f"((d)[0]), "=f"((d)[1]), "=f"((d)[2]), "=f"((d)[3]) \
        : "r"((a)[0]), "r"((a)[1]), "r"((a)[2]), "r"((a)[3]), "r"(b0_), "r"(b1_), \
          "f"(0.0f))

#define CP16(s, g) \
    asm volatile("cp.async.cg.shared.global [%0], [%1], 16;" :: "r"(s), "l"(g) : "memory")
#define CP_COMMIT() asm volatile("cp.async.commit_group;" ::: "memory")
#define CP_WAIT1()  asm volatile("cp.async.wait_group 1;" ::: "memory")
#define CP_WAIT0()  asm volatile("cp.async.wait_group 0;" ::: "memory")
#define LDS128(v, a) \
    asm volatile("ld.shared.v4.b32 {%0,%1,%2,%3}, [%4];" \
        : "=r"((v).x), "=r"((v).y), "=r"((v).z), "=r"((v).w) : "r"(a))
#define LDS64U(v, a) \
    asm volatile("ld.shared.v2.b32 {%0,%1}, [%2];" : "=r"((v).x), "=r"((v).y) : "r"(a))
#define STS128(a, v0, v1, v2, v3) \
    asm volatile("st.shared.v4.b32 [%0], {%1,%2,%3,%4};" \
        :: "r"(a), "r"(v0), "r"(v1), "r"(v2), "r"(v3) : "memory")

// ---------------- weight prep: scale x256, fp16 split, fragment pack -------
__global__ void prep_bfrag(const float* __restrict__ w) {
    int i = blockIdx.x * blockDim.x + threadIdx.x;   // (step*8 + tile)*32 + lane
    if (i >= 128 * 8 * 32) return;
    int lane = i & 31;
    int tile = (i >> 5) & 7;
    int step = i >> 8;
    int e = tile * 8 + (lane >> 2);
    int t4 = lane & 3;
    int k0 = step * 16 + 2 * t4;
    const float* wr = w + (size_t)e * D;
    uint32_t h0, m0, h1, m1;
    splitp(wr[k0] * 256.0f,     wr[k0 + 1] * 256.0f, h0, m0);   // k pair low
    splitp(wr[k0 + 8] * 256.0f, wr[k0 + 9] * 256.0f, h1, m1);   // k pair +8
    *reinterpret_cast<uint4*>(g_bfrag + step * BSTEP + tile * 512 + lane * 16) =
        make_uint4(h0, h1, m0, m1);
}

// stage B chunk c into ring stage s (16KB), one commit group
static __device__ __forceinline__ void stage_b(uint32_t sbase, int c, int s, int tid) {
    const unsigned char* bsrc = g_bfrag + (size_t)c * BCHUNK;
    uint32_t bd = sbase + s * BCHUNK;
    #pragma unroll
    for (int p = 0; p < 4; ++p) {
        int u = tid + p * 256;
        CP16(bd + u * 16, bsrc + u * 16);
    }
    CP_COMMIT();
}

// split 16 x floats and store as 8 packed (h,m) uint2 pairs: 4 x STS.128
static __device__ __forceinline__ void sts_xsplit(uint32_t dst, const float4* v) {
    #pragma unroll
    for (int j = 0; j < 4; ++j) {
        uint32_t h0, m0, h1, m1;
        splitp(v[j].x, v[j].y, h0, m0);
        splitp(v[j].z, v[j].w, h1, m1);
        STS128(dst + j * 16, h0, m0, h1, m1);
    }
}

// ---------------- main fused kernel ----------------
__global__ void __launch_bounds__(256, 2)
moe_gate(const float* __restrict__ x, float* __restrict__ out, int Ntok) {
    extern __shared__ __align__(16) float smemf[];
    const uint32_t sbase = smem_u32(smemf);
    const int tid = threadIdx.x;
    const int wid = tid >> 5;
    const int lane = tid & 31;
    const int g = lane >> 2;
    const int t4 = lane & 3;
    const int tg = wid >> 1;          // token group 0..3 (16 tokens, m16)
    const int eh = wid & 1;           // expert half 0..1 (32 experts, n32)
    const size_t t0 = (size_t)blockIdx.x * TB;

    float chx[4][4], ms[4][4], cc[4][4];
    #pragma unroll
    for (int i = 0; i < 4; ++i)
        #pragma unroll
        for (int j = 0; j < 4; ++j) { ms[i][j] = 0.0f; cc[i][j] = 0.0f; }

    // x staging role: thread -> (row, 16 consecutive k)
    const int xrow = tid >> 2;
    const int xkq = tid & 3;                     // quarter of k64
    const float* xgp = x + (t0 + xrow) * D + xkq * 16;
    const uint32_t xsts = sbase + XBASE + xrow * XSTRIDE + xkq * 64;

    // prologue: LDG+split+STS x chunk 0; LDG chunk 1 into regs; cp.async B0,B1
    float4 xr[4];
    {
        float4 v[4];
        #pragma unroll
        for (int j = 0; j < 4; ++j) v[j] = *reinterpret_cast<const float4*>(xgp + 4 * j);
        sts_xsplit(xsts, v);
        #pragma unroll
        for (int j = 0; j < 4; ++j) xr[j] = *reinterpret_cast<const float4*>(xgp + 64 + 4 * j);
    }
    stage_b(sbase, 0, 0, tid);
    stage_b(sbase, 1, 1, tid);

    // A fragment gather base: rows tg*16 + {g, g+8}, pair t4 (+4)
    const uint32_t xfrag = sbase + XBASE + (tg * 16 + g) * XSTRIDE + t4 * 8;

    int st = 0;       // ch % 3
    for (int ch = 0; ch < NCH; ++ch) {
        if (ch + 1 < NCH) CP_WAIT1(); else CP_WAIT0();
        __syncthreads();   // B(ch)+x(ch) visible; B stage (ch+2)%3 and
                           // x stage (ch+1)&1 are read-free

        // stage forward: STS x(ch+1) from regs; cp.async B(ch+2); LDG x(ch+2)
        if (ch + 1 < NCH)
            sts_xsplit(xsts + ((ch + 1) & 1) * XCH, xr);
        if (ch + 2 < NCH) {
            stage_b(sbase, ch + 2, (st + 2) % 3, tid);
            const float* nx = xgp + (size_t)(ch + 2) * 64;
            #pragma unroll
            for (int j = 0; j < 4; ++j) xr[j] = *reinterpret_cast<const float4*>(nx + 4 * j);
        }

        const uint32_t bstg = sbase + st * BCHUNK + eh * 2048 + lane * 16;
        const uint32_t xstg = xfrag + (ch & 1) * XCH;

        // preload step-0 A fragments: (h,m) packed pairs
        uint2 u0, u1, u2, u3;
        LDS64U(u0, xstg);                     // row g,   pair t4
        LDS64U(u1, xstg + 8 * XSTRIDE);       // row g+8, pair t4
        LDS64U(u2, xstg + 32);                // row g,   pair t4+4
        LDS64U(u3, xstg + 8 * XSTRIDE + 32);  // row g+8, pair t4+4

        #pragma unroll
        for (int s4 = 0; s4 < 4; ++s4) {
            // shadow-prefetch next step's A fragments
            uint2 n0, n1, n2, n3;
            if (s4 < 3) {
                const uint32_t xp = xstg + (s4 + 1) * 64;
                LDS64U(n0, xp);
                LDS64U(n1, xp + 8 * XSTRIDE);
                LDS64U(n2, xp + 32);
                LDS64U(n3, xp + 8 * XSTRIDE + 32);
            }

            uint32_t Ah[4] = {u0.x, u1.x, u2.x, u3.x};
            uint32_t Am[4] = {u0.y, u1.y, u2.y, u3.y};

            const uint32_t bb = bstg + s4 * BSTEP;
            uint4 b0, b1, b2, b3;
            LDS128(b0, bb);
            LDS128(b1, bb + 512);
            LDS128(b2, bb + 1024);
            LDS128(b3, bb + 1536);

            // corrections (Am x wh) first -- independent of chx
            MMA(cc[0], Am, b0.x, b0.y);
            MMA(cc[1], Am, b1.x, b1.y);
            MMA(cc[2], Am, b2.x, b2.y);
            MMA(cc[3], Am, b3.x, b3.y);
            // hh chunk terms (restart onto zero C at chunk head)
            if (s4 == 0) {
                MMA_ZC(chx[0], Ah, b0.x, b0.y);
                MMA_ZC(chx[1], Ah, b1.x, b1.y);
                MMA_ZC(chx[2], Ah, b2.x, b2.y);
                MMA_ZC(chx[3], Ah, b3.x, b3.y);
            } else {
                MMA(chx[0], Ah, b0.x, b0.y);
                MMA(chx[1], Ah, b1.x, b1.y);
                MMA(chx[2], Ah, b2.x, b2.y);
                MMA(chx[3], Ah, b3.x, b3.y);
            }
            // corrections (Ah x wm) -- dependent pairs 8 MMAs apart
            MMA(cc[0], Ah, b0.z, b0.w);
            MMA(cc[1], Ah, b1.z, b1.w);
            MMA(cc[2], Ah, b2.z, b2.w);
            MMA(cc[3], Ah, b3.z, b3.w);

            u0 = n0; u1 = n1; u2 = n2; u3 = n3;
        }
        // rebase every k64 chunk: master += chunk (RN fp32, unbiased)
        #pragma unroll
        for (int i = 0; i < 4; ++i)
            #pragma unroll
            for (int j = 0; j < 4; ++j) ms[i][j] += chx[i][j];

        st = (st == 2) ? 0 : st + 1;
    }
    __syncthreads();   // all compute done before epilogue smem reuse

    // -------- epilogue: logits -> smem (x 2^-8), softmax + top-8 ------------
    float* L = smemf;   // [64][EPI_STRIDE]
    {
        int r0 = tg * 16 + g;
        #pragma unroll
        for (int j = 0; j < 4; ++j) {
            int n0 = eh * 32 + j * 8 + 2 * t4;
            *reinterpret_cast<float2*>(L + r0 * EPI_STRIDE + n0) =
                make_float2((ms[j][0] + cc[j][0]) * OSCALE,
                            (ms[j][1] + cc[j][1]) * OSCALE);
            *reinterpret_cast<float2*>(L + (r0 + 8) * EPI_STRIDE + n0) =
                make_float2((ms[j][2] + cc[j][2]) * OSCALE,
                            (ms[j][3] + cc[j][3]) * OSCALE);
        }
    }
    __syncthreads();

    if (tid < TB) {
        float pv[64];
        const float* Lr = L + tid * EPI_STRIDE;
        #pragma unroll
        for (int c = 0; c < 16; ++c) {
            float4 v = *reinterpret_cast<const float4*>(Lr + 4 * c);
            pv[4 * c] = v.x; pv[4 * c + 1] = v.y;
            pv[4 * c + 2] = v.z; pv[4 * c + 3] = v.w;
        }
        float mx = pv[0];
        #pragma unroll
        for (int c = 1; c < 64; ++c) mx = fmaxf(mx, pv[c]);
        float s = 0.0f;
        #pragma unroll
        for (int c = 0; c < 64; ++c) { pv[c] = __expf(pv[c] - mx); s += pv[c]; }
        float inv = 1.0f / s;
        #pragma unroll
        for (int c = 0; c < 64; ++c) pv[c] *= inv;

        const size_t gt = t0 + tid;
        float* pr = out + gt * 64;
        #pragma unroll
        for (int c = 0; c < 16; ++c)
            *reinterpret_cast<float4*>(pr + 4 * c) =
                make_float4(pv[4 * c], pv[4 * c + 1], pv[4 * c + 2], pv[4 * c + 3]);

        // top-8 insertion; strict '>' keeps smaller index on ties (lax.top_k)
        float tv[8]; int ti[8];
        #pragma unroll
        for (int r = 0; r < 8; ++r) { tv[r] = -1.0f; ti[r] = 0; }
        #pragma unroll
        for (int j = 0; j < 64; ++j) {
            float v = pv[j];
            if (v > tv[7]) {
                tv[7] = v; ti[7] = j;
                #pragma unroll
                for (int q = 7; q > 0; --q) {
                    bool sw = tv[q] > tv[q - 1];
                    float fv = sw ? tv[q - 1] : tv[q];
                    int   fi = sw ? ti[q - 1] : ti[q];
                    tv[q - 1] = sw ? tv[q] : tv[q - 1];
                    ti[q - 1] = sw ? ti[q] : ti[q - 1];
                    tv[q] = fv; ti[q] = fi;
                }
            }
        }
        const size_t tvo = (size_t)Ntok * 64;
        const size_t ixo = tvo + (size_t)Ntok * 8;
        *reinterpret_cast<float4*>(out + tvo + gt * 8)     =
            make_float4(tv[0], tv[1], tv[2], tv[3]);
        *reinterpret_cast<float4*>(out + tvo + gt * 8 + 4) =
            make_float4(tv[4], tv[5], tv[6], tv[7]);
        *reinterpret_cast<float4*>(out + ixo + gt * 8)     =
            make_float4((float)ti[0], (float)ti[1], (float)ti[2], (float)ti[3]);
        *reinterpret_cast<float4*>(out + ixo + gt * 8 + 4) =
            make_float4((float)ti[4], (float)ti[5], (float)ti[6], (float)ti[7]);
    }
}

extern "C" void kernel_launch(void* const* d_in, const int* in_sizes, int n_in,
                              void* d_out, int out_size) {
    const float* x = (const float*)d_in[0];
    const float* w = (const float*)d_in[1];
    float* out = (float*)d_out;
    int Ntok = in_sizes[0] / D;     // 32768

    cudaFuncSetAttribute(moe_gate, cudaFuncAttributeMaxDynamicSharedMemorySize, SMEM_SZ);
    prep_bfrag<<<(128 * 8 * 32 + 255) / 256, 256>>>(w);
    moe_gate<<<Ntok / TB, 256, SMEM_SZ>>>(x, out, Ntok);
}